// round 9
// baseline (speedup 1.0000x reference)
#include <cuda_runtime.h>
#include <cstdint>

// Problem constants
#define EDIM   127
#define BN     2048                 // B*N
#define BNE    260096               // B*N*E

#define CT      512
#define NODES   16
#define GROUPS  128                 // BN / NODES

// Smem layout (floats). Total 56976 floats = 227904 B.
#define OFF_W     0                 // 6 slots * 256 rows * 32 = 49152
#define OFF_B3    49152             // 6 * 256 = 1536
#define OFF_H2    50688             // 16 nodes * 132 = 2112 (msg buffer aliases this)
#define OFF_AUXA  52800             // 16 * 65 = 1040  (c00|s0|ws1|b01)
#define OFF_V11   53840             // 16 * 49 float4 = 3136 floats
#define SMF       56976
#define SMB       (SMF * 4)

#define H2PAD  132
#define AXPAD  65
#define V11PAD 49

#define OUT1_BASE4 1040384          // (BNE*16)/4

__device__ __forceinline__ float warp_sum(float v) {
    v += __shfl_xor_sync(0xffffffffu, v, 16);
    v += __shfl_xor_sync(0xffffffffu, v, 8);
    v += __shfl_xor_sync(0xffffffffu, v, 4);
    v += __shfl_xor_sync(0xffffffffu, v, 2);
    v += __shfl_xor_sync(0xffffffffu, v, 1);
    return v;
}

// packed fp32x2 FMA: d = a*b + d
__device__ __forceinline__ void ffma2(unsigned long long& d,
                                      unsigned long long a,
                                      unsigned long long b) {
    asm("fma.rn.f32x2 %0, %1, %2, %0;" : "+l"(d) : "l"(a), "l"(b));
}

// one 16-float half-row dot (bias pre-halved; both khalves add it, shfl sums)
__device__ __forceinline__ float dot_row(const float* wrow, float binit,
                                         const ulonglong2& hp0, const ulonglong2& hp1,
                                         const ulonglong2& hp2, const ulonglong2& hp3)
{
    const ulonglong2* wp = (const ulonglong2*)wrow;
    unsigned long long acA = (unsigned long long)__float_as_uint(binit);
    unsigned long long acB = 0ull;
    ulonglong2 wa = wp[0], wb = wp[1];
    ffma2(acA, wa.x, hp0.x); ffma2(acB, wa.y, hp0.y);
    ffma2(acA, wb.x, hp1.x); ffma2(acB, wb.y, hp1.y);
    wa = wp[2]; wb = wp[3];
    ffma2(acA, wa.x, hp2.x); ffma2(acB, wa.y, hp2.y);
    ffma2(acA, wb.x, hp3.x); ffma2(acB, wb.y, hp3.y);
    return (__uint_as_float((unsigned)acA) + __uint_as_float((unsigned)(acA >> 32)))
         + (__uint_as_float((unsigned)acB) + __uint_as_float((unsigned)(acB >> 32)));
}

extern "C" __global__ void __launch_bounds__(CT, 1)
fused_kernel(const float* __restrict__ r,
             const float* __restrict__ src0,
             const float* __restrict__ src1,
             const float* __restrict__ b00g,
             const float* __restrict__ b01g,
             const float* __restrict__ b10g,
             const float* __restrict__ b11g,
             const float* __restrict__ w1,
             const float* __restrict__ b1,
             const float* __restrict__ g1,
             const float* __restrict__ be1,
             const float* __restrict__ w2,
             const float* __restrict__ b2,
             const float* __restrict__ g2,
             const float* __restrict__ be2,
             const float* __restrict__ w300, const float* __restrict__ b300,
             const float* __restrict__ w301, const float* __restrict__ b301,
             const float* __restrict__ w310, const float* __restrict__ b310,
             const float* __restrict__ w311, const float* __restrict__ b311,
             float4* __restrict__ out)
{
    extern __shared__ float sm[];
    float* Wsm = sm + OFF_W;     // [slot][rowq = i*16+gq][32]
    float* b3s = sm + OFF_B3;    // [slot][rowq]
    float* h2s = sm + OFF_H2;    // [node*H2PAD + m*32 + k]
    float* axA = sm + OFF_AUXA;  // [node*AXPAD + {0:c00,16:s0,32:ws1,48:b01}]
    float4* v4 = (float4*)(sm + OFF_V11);  // [node*V11PAD + X], a in xyz

    const int t    = threadIdx.x;
    const int lane = t & 31;
    const int w    = t >> 5;           // warp id (= node in prologue, = i in main)
    const int blk  = blockIdx.x;

    // ---- stage 6 weight slots: dest row rowq = i*16+gq, k-contiguous ----
    float4* Wsm4 = (float4*)Wsm;
    for (int d4 = t; d4 < 12288; d4 += CT) {
        int slot = d4 >> 11, rem = d4 & 2047;
        int rowq = rem >> 3, k4 = rem & 7;
        const float4* src; int srow;
        if (slot == 0)      { src = (const float4*)w300; srow = rowq; }
        else if (slot == 1) { src = (const float4*)w301; srow = rowq; }
        else if (slot == 2) { src = (const float4*)w310; srow = rowq; }
        else {
            src = (const float4*)w311;
            srow = (rowq >> 4) * 48 + (slot - 3) * 16 + (rowq & 15);
        }
        Wsm4[slot * 2048 + rowq * 8 + k4] = src[srow * 8 + k4];
    }
    for (int idx = t; idx < 1536; idx += CT) {
        int slot = idx >> 8, rowq = idx & 255;
        const float* bs; int srow;
        if (slot == 0)      { bs = b300; srow = rowq; }
        else if (slot == 1) { bs = b301; srow = rowq; }
        else if (slot == 2) { bs = b310; srow = rowq; }
        else { bs = b311; srow = (rowq >> 4) * 48 + (slot - 3) * 16 + (rowq & 15); }
        b3s[idx] = bs[srow];
    }

    // ---- prologue: warp w = node, computes 4 MLPs + aux ----
    const int node0 = blk * NODES + w;
    const int eb    = node0 * EDIM;
    const float x   = r[eb];
    const int k     = lane;

    #pragma unroll 1
    for (int m = 0; m < 4; m++) {
        float v = fmaf(x, w1[m * 32 + k], b1[m * 32 + k]);
        float mu = warp_sum(v) * (1.f / 32.f);
        float d = v - mu;
        float var = warp_sum(d * d) * (1.f / 32.f);
        v = fmaf(d * rsqrtf(var + 1e-5f), g1[m * 32 + k], be1[m * 32 + k]);
        v = fmaxf(v, 0.f);

        float w2reg[32];
        const float4* w2r = (const float4*)(w2 + (m * 32 + k) * 32);
        #pragma unroll
        for (int q = 0; q < 8; q++) {
            float4 tmp = w2r[q];
            w2reg[q * 4 + 0] = tmp.x; w2reg[q * 4 + 1] = tmp.y;
            w2reg[q * 4 + 2] = tmp.z; w2reg[q * 4 + 3] = tmp.w;
        }
        float a0 = b2[m * 32 + k], a1 = 0.f, a2 = 0.f, a3 = 0.f;
        #pragma unroll
        for (int kk = 0; kk < 8; kk++) {
            a0 = fmaf(__shfl_sync(0xffffffffu, v, kk),      w2reg[kk],      a0);
            a1 = fmaf(__shfl_sync(0xffffffffu, v, kk + 8),  w2reg[kk + 8],  a1);
            a2 = fmaf(__shfl_sync(0xffffffffu, v, kk + 16), w2reg[kk + 16], a2);
            a3 = fmaf(__shfl_sync(0xffffffffu, v, kk + 24), w2reg[kk + 24], a3);
        }
        float acc = (a0 + a1) + (a2 + a3);
        float mu2 = warp_sum(acc) * (1.f / 32.f);
        float d2 = acc - mu2;
        float var2 = warp_sum(d2 * d2) * (1.f / 32.f);
        acc = fmaf(d2 * rsqrtf(var2 + 1e-5f), g2[m * 32 + k], be2[m * 32 + k]);
        acc = fmaxf(acc, 0.f);
        h2s[w * H2PAD + m * 32 + k] = acc;
    }

    if (lane < 16) {
        const int j = lane;
        float s0v = src0[eb * 16 + j];
        float s1a = src1[eb * 48 + j * 3 + 0];
        float s1b = src1[eb * 48 + j * 3 + 1];
        float s1c = src1[eb * 48 + j * 3 + 2];
        axA[w * AXPAD + j]      = b00g[node0] * s0v;                 // c00
        axA[w * AXPAD + 16 + j] = s0v;                               // s0
        axA[w * AXPAD + 32 + j] = b10g[node0 * 3 + 0] * s1a          // ws1
                                + b10g[node0 * 3 + 1] * s1b
                                + b10g[node0 * 3 + 2] * s1c;
        if (j < 3) axA[w * AXPAD + 48 + j] = b01g[node0 * 3 + j];
        #pragma unroll
        for (int f = 0; f < 3; f++) {
            float v0 = b11g[node0 * 27 + 0 + f] * s1a
                     + b11g[node0 * 27 + 3 + f] * s1b
                     + b11g[node0 * 27 + 6 + f] * s1c;
            float v1 = b11g[node0 * 27 + 9 + f] * s1a
                     + b11g[node0 * 27 + 12 + f] * s1b
                     + b11g[node0 * 27 + 15 + f] * s1c;
            float v2 = b11g[node0 * 27 + 18 + f] * s1a
                     + b11g[node0 * 27 + 21 + f] * s1b
                     + b11g[node0 * 27 + 24 + f] * s1c;
            v4[w * V11PAD + j * 3 + f] = make_float4(v0, v1, v2, 0.f);
        }
    }
    __syncthreads();

    // ---- main loop: warp = out-channel i; lane = (node, khalf) ----
    const int i     = w;
    const int node  = lane >> 1;
    const int khalf = lane & 1;

    const float* axn  = axA + node * AXPAD;
    const float4* v4n = v4 + node * V11PAD;
    const float b01r0 = axn[48], b01r1 = axn[49], b01r2 = axn[50];

    const ulonglong2* hbase = (const ulonglong2*)(h2s + node * H2PAD + khalf * 16);

    float z0 = 0.f, y0 = 0.f, y1 = 0.f, y2 = 0.f;
    ulonglong2 hp0, hp1, hp2, hp3;

#define LOAD_HP(m) { const ulonglong2* hp = hbase + (m) * 8; \
    hp0 = hp[0]; hp1 = hp[1]; hp2 = hp[2]; hp3 = hp[3]; }

    // ch0: slot0, m0 -> msg0 via c00
    LOAD_HP(0);
    {
        const float* wb = Wsm + (0 * 256 + i * 16) * 32 + khalf * 16;
        const float* bb = b3s + 0 * 256 + i * 16;
        #pragma unroll 4
        for (int gq = 0; gq < 16; gq++) {
            float s = dot_row(wb + gq * 32, 0.5f * bb[gq], hp0, hp1, hp2, hp3);
            z0 = fmaf(s, axn[gq], z0);
        }
    }
    // ch1: slot1, m1 -> msg1 via s0 * b01[a]
    LOAD_HP(1);
    {
        const float* wb = Wsm + (1 * 256 + i * 16) * 32 + khalf * 16;
        const float* bb = b3s + 1 * 256 + i * 16;
        #pragma unroll 4
        for (int gq = 0; gq < 16; gq++) {
            float s = dot_row(wb + gq * 32, 0.5f * bb[gq], hp0, hp1, hp2, hp3);
            float tt = s * axn[16 + gq];
            y0 = fmaf(tt, b01r0, y0);
            y1 = fmaf(tt, b01r1, y1);
            y2 = fmaf(tt, b01r2, y2);
        }
    }
    // ch2: slot2, m2 -> msg0 via ws1
    LOAD_HP(2);
    {
        const float* wb = Wsm + (2 * 256 + i * 16) * 32 + khalf * 16;
        const float* bb = b3s + 2 * 256 + i * 16;
        #pragma unroll 4
        for (int gq = 0; gq < 16; gq++) {
            float s = dot_row(wb + gq * 32, 0.5f * bb[gq], hp0, hp1, hp2, hp3);
            z0 = fmaf(s, axn[32 + gq], z0);
        }
    }
    // ch3..5: slots 3..5, m3 -> msg1 via v11[a][cc*16+gq]
    LOAD_HP(3);
    #pragma unroll 1
    for (int cc = 0; cc < 3; cc++) {
        const float* wb = Wsm + ((3 + cc) * 256 + i * 16) * 32 + khalf * 16;
        const float* bb = b3s + (3 + cc) * 256 + i * 16;
        const float4* vv = v4n + cc * 16;
        #pragma unroll 4
        for (int gq = 0; gq < 16; gq++) {
            float s = dot_row(wb + gq * 32, 0.5f * bb[gq], hp0, hp1, hp2, hp3);
            float4 vg = vv[gq];
            y0 = fmaf(s, vg.x, y0);
            y1 = fmaf(s, vg.y, y1);
            y2 = fmaf(s, vg.z, y2);
        }
    }

    // combine k-halves (adjacent lanes)
    z0 += __shfl_xor_sync(0xffffffffu, z0, 1);
    y0 += __shfl_xor_sync(0xffffffffu, y0, 1);
    y1 += __shfl_xor_sync(0xffffffffu, y1, 1);
    y2 += __shfl_xor_sync(0xffffffffu, y2, 1);

    // ---- write messages into smem (reuse h2 region), then fan out ----
    __syncthreads();                 // all h2s reads complete
    float* msg = h2s;                // [node][64] = msg0[16] | msg1[48]
    if (khalf == 0) {
        msg[node * 64 + i] = z0;
        msg[node * 64 + 16 + i * 3 + 0] = y0;
        msg[node * 64 + 16 + i * 3 + 1] = y1;
        msg[node * 64 + 16 + i * 3 + 2] = y2;
    }
    __syncthreads();

    // ---- fused broadcast: this block's 16 nodes -> all 127 edges ----
    const float4* mq = (const float4*)msg;
    const int bn0 = blk * NODES;
    int s12 = t % 12;
    int sb = s12 + 8; if (sb >= 12) sb -= 12;   // (t+512) % 12
    int sc = s12 + 4; if (sc >= 12) sc -= 12;   // (t+1024) % 12

    #pragma unroll 1
    for (int nn = 0; nn < NODES; nn++) {
        const float4* mrow = mq + nn * 16;      // [0..3]=msg0, [4..15]=msg1
        // out0: 508 float4, period 4
        float4* o0 = out + (size_t)(bn0 + nn) * 508;
        if (t < 508) o0[t] = mrow[t & 3];
        // out1: 1524 float4, period 12
        float4* o1 = out + OUT1_BASE4 + (size_t)(bn0 + nn) * 1524;
        o1[t]       = mrow[4 + s12];
        o1[t + 512] = mrow[4 + sb];
        if (t < 500) o1[t + 1024] = mrow[4 + sc];
    }
}

extern "C" void kernel_launch(void* const* d_in, const int* in_sizes, int n_in,
                              void* d_out, int out_size)
{
    const float* r    = (const float*)d_in[0];
    const float* src0 = (const float*)d_in[1];
    const float* src1 = (const float*)d_in[2];
    const float* b00  = (const float*)d_in[3];
    const float* b01  = (const float*)d_in[4];
    const float* b10  = (const float*)d_in[5];
    const float* b11  = (const float*)d_in[6];
    const float* w1   = (const float*)d_in[7];
    const float* b1   = (const float*)d_in[8];
    const float* g1   = (const float*)d_in[9];
    const float* be1  = (const float*)d_in[10];
    const float* w2   = (const float*)d_in[11];
    const float* b2   = (const float*)d_in[12];
    const float* g2   = (const float*)d_in[13];
    const float* be2  = (const float*)d_in[14];
    const float* w300 = (const float*)d_in[15];
    const float* b300 = (const float*)d_in[16];
    const float* w301 = (const float*)d_in[17];
    const float* b301 = (const float*)d_in[18];
    const float* w310 = (const float*)d_in[19];
    const float* b310 = (const float*)d_in[20];
    const float* w311 = (const float*)d_in[21];
    const float* b311 = (const float*)d_in[22];

    cudaFuncSetAttribute(fused_kernel,
                         cudaFuncAttributeMaxDynamicSharedMemorySize, SMB);

    fused_kernel<<<GROUPS, CT, SMB>>>(
        r, src0, src1, b00, b01, b10, b11,
        w1, b1, g1, be1, w2, b2, g2, be2,
        w300, b300, w301, b301, w310, b310, w311, b311,
        (float4*)d_out);
}